// round 15
// baseline (speedup 1.0000x reference)
#include <cuda_runtime.h>
#include <cuda_bf16.h>
#include <cuda_fp16.h>
#include <cstdint>

#define NTOK 8192
#define DIN  256
#define DOUT 256
#define NE   16
#define NH   512

// ---------------------------------------------------------------------------
// Device scratch
// ---------------------------------------------------------------------------
__device__ int   g_cnt[NE];
__device__ int   g_tilecnt[64];
__device__ int   g_rtok[NE * NTOK];
__device__ float g_rgate[NE * NTOK];
__device__ float g_logits[NTOK * NE];

__device__ __half g_xh[NTOK * DIN], g_xlo[NTOK * DIN];
__device__ __half g_gwh[NH * DIN],  g_gwl[NH * DIN];    // gate_w planes [n=512][k=256]
__device__ __half g_gowTh[NE * NH], g_gowTl[NE * NH];   // gate_out_w planes [e][k=512]
__device__ __half g_w1T[NE * NH * DIN];     // [e][n=512][k=256]
__device__ __half g_w2T[NE * NH * NH];      // [e][512][512]
__device__ __half g_w3T[NE * DOUT * NH];    // [e][256][512]

// ---------------------------------------------------------------------------
// PTX helpers (compute_103-safe: cp.async + ldmatrix + mma.sync only)
// ---------------------------------------------------------------------------
__device__ __forceinline__ uint32_t smem_u32(const void* p) {
    uint32_t a;
    asm("{ .reg .u64 t; cvta.to.shared.u64 t, %1; cvt.u32.u64 %0, t; }" : "=r"(a) : "l"(p));
    return a;
}
#define CP16(dst, src) \
    asm volatile("cp.async.cg.shared.global [%0], [%1], 16;" :: "r"(dst), "l"(src) : "memory")
#define CP_COMMIT() asm volatile("cp.async.commit_group;" ::: "memory")
#define CP_WAIT(n)  asm volatile("cp.async.wait_group %0;" :: "n"(n) : "memory")

#define LDSM4(r, addr) \
    asm volatile("ldmatrix.sync.aligned.m8n8.x4.shared.b16 {%0,%1,%2,%3}, [%4];" \
        : "=r"((r)[0]), "=r"((r)[1]), "=r"((r)[2]), "=r"((r)[3]) : "r"(addr))

#define MMA16816H(c, a, b) \
    asm volatile("mma.sync.aligned.m16n8k16.row.col.f32.f16.f16.f32 " \
        "{%0,%1,%2,%3}, {%4,%5,%6,%7}, {%8,%9}, {%0,%1,%2,%3};" \
        : "+f"((c)[0]), "+f"((c)[1]), "+f"((c)[2]), "+f"((c)[3]) \
        : "r"((a)[0]), "r"((a)[1]), "r"((a)[2]), "r"((a)[3]), "r"((b)[0]), "r"((b)[1]))

// Pair-packed 64B-row swizzle: logical (row, k-unit) in 128B phys rows.
__device__ __forceinline__ uint32_t sw32(int row, int u) {
    return (uint32_t)((row >> 1) * 128 +
                      (((((row & 1) << 2) + u) ^ ((row >> 1) & 7)) << 4));
}

// ---------------------------------------------------------------------------
// prep_gate: x -> hi/lo fp16; gate_w -> transposed hi/lo; logits <- bias;
// gate_out_w -> transposed hi/lo planes; zero g_cnt / g_tilecnt.
//   [0,2048) x | [2048,2176) gw | [2176,2688) logits | 2688 zero | 2689 gowT
// ---------------------------------------------------------------------------
__global__ __launch_bounds__(256) void prep_gate_kernel(
    const float* __restrict__ x, const float* __restrict__ gw,
    const float* __restrict__ gob, const float* __restrict__ gow)
{
    const int bid = blockIdx.x;
    const int tid = threadIdx.x;

    if (bid < 2048) {
        int base = bid * 512 + tid;
#pragma unroll
        for (int j = 0; j < 2; ++j) {
            int i = base + j * 256;
            float2 v = ((const float2*)x)[i];
            __half h0 = __float2half_rn(v.x), h1 = __float2half_rn(v.y);
            __half l0 = __float2half_rn(v.x - __half2float(h0));
            __half l1 = __float2half_rn(v.y - __half2float(h1));
            __half2 hh = __halves2half2(h0, h1), ll = __halves2half2(l0, l1);
            ((uint32_t*)g_xh)[i]  = *(uint32_t*)&hh;
            ((uint32_t*)g_xlo)[i] = *(uint32_t*)&ll;
        }
        return;
    }
    if (bid < 2176) {
        __shared__ float t[32][33];
        const int tx = tid & 31, ty = tid >> 5;
        int r = bid - 2048;
        int n0 = (r & 15) * 32, k0 = (r >> 4) * 32;
#pragma unroll
        for (int i = 0; i < 4; ++i)
            t[ty + 8 * i][tx] = gw[(long)(k0 + ty + 8 * i) * NH + n0 + tx];
        __syncthreads();
#pragma unroll
        for (int i = 0; i < 4; ++i) {
            float v = t[tx][ty + 8 * i];
            __half h = __float2half_rn(v);
            __half l = __float2half_rn(v - __half2float(h));
            size_t idx = (size_t)(n0 + ty + 8 * i) * DIN + k0 + tx;
            g_gwh[idx] = h;
            g_gwl[idx] = l;
        }
        return;
    }
    if (bid < 2688) {
        int i = (bid - 2176) * 256 + tid;
        g_logits[i] = gob[i & 15];
        return;
    }
    if (bid == 2688) {
        if (tid < NE) g_cnt[tid] = 0;
        if (tid < 64) g_tilecnt[tid] = 0;
        return;
    }
    // bid == 2689: gate_out_w [512][16] -> planes [16][512] hi/lo
#pragma unroll 4
    for (int i = 0; i < 32; ++i) {
        int idx = tid + i * 256;          // 8192
        int k = idx >> 4, ee = idx & 15;
        float v = gow[k * NE + ee];
        __half h = __float2half_rn(v);
        g_gowTh[ee * NH + k] = h;
        g_gowTl[ee * NH + k] = __float2half_rn(v - __half2float(h));
    }
}

// ---------------------------------------------------------------------------
// prep_expert: 3 weight transposes -> single fp16 planes.
// ---------------------------------------------------------------------------
__global__ __launch_bounds__(256) void prep_expert_kernel(
    const float* __restrict__ w1, const float* __restrict__ w2,
    const float* __restrict__ w3)
{
    const int bid = blockIdx.x;
    const int tid = threadIdx.x;
    __shared__ float t[32][33];
    const int tx = tid & 31, ty = tid >> 5;

    const float* src; long rs; int K, N, e, n0, k0;
    __half* dh;
    if (bid < 2048) {                    // w1
        int l = bid;
        e = l >> 7; int r = l & 127;
        n0 = (r & 15) * 32; k0 = (r >> 4) * 32;
        src = w1 + e * NH; rs = (long)NE * NH; K = DIN; N = NH;
        dh = g_w1T;
    } else if (bid < 6144) {             // w2
        int l = bid - 2048;
        e = l >> 8; int r = l & 255;
        n0 = (r & 15) * 32; k0 = (r >> 4) * 32;
        src = w2 + e * NH; rs = (long)NE * NH; K = NH; N = NH;
        dh = g_w2T;
    } else {                             // w3
        int l = bid - 6144;
        e = l >> 7; int r = l & 127;
        n0 = (r & 7) * 32; k0 = (r >> 3) * 32;
        src = w3 + e * DOUT; rs = (long)NE * DOUT; K = NH; N = DOUT;
        dh = g_w3T;
    }
    dh += (size_t)e * N * K;

#pragma unroll
    for (int i = 0; i < 4; ++i)
        t[ty + 8 * i][tx] = src[(long)(k0 + ty + 8 * i) * rs + n0 + tx];
    __syncthreads();
#pragma unroll
    for (int i = 0; i < 4; ++i)
        dh[(size_t)(n0 + ty + 8 * i) * K + k0 + tx] = __float2half_rn(t[tx][ty + 8 * i]);
}

// ---------------------------------------------------------------------------
// gate_mma: 3-product split-fp16 hidden GEMM + MMA logit epilogue + (last CTA
// of each tile) routing. Grid (64, 2).
// ---------------------------------------------------------------------------
#define GSTG 49152

__global__ __launch_bounds__(512, 1) void gate_mma_kernel(
    const float* __restrict__ gb)
{
    const int tile  = blockIdx.x;
    const int nbase = blockIdx.y * 256;

    extern __shared__ char smp[];
    const uint32_t smb = smem_u32(smp);
    __shared__ float sbias[256];
    __shared__ int   s_flag;

    const int tid  = threadIdx.x;
    const int wid  = tid >> 5, lane = tid & 31;
    const int wm   = wid & 3,  wn   = wid >> 2;

    if (tid < 256) sbias[tid] = gb[nbase + tid];
    __syncthreads();

    auto load_chunk = [&](int ch) {
        const int kbase = ch * 32;
        const uint32_t sb = smb + (ch & 3) * GSTG;
        {
            int row = tid >> 2, u = tid & 3;
            uint32_t d = sb + sw32(row, u);
            long arow = (long)tile * 128 + row;
            CP16(d,        g_xh  + arow * DIN + kbase + u * 8);
            CP16(d + 8192, g_xlo + arow * DIN + kbase + u * 8);
        }
#pragma unroll
        for (int i = 0; i < 2; ++i) {
            int idx = tid + i * 512;
            int row = idx >> 2, u = idx & 3;
            uint32_t d = sb + 16384 + sw32(row, u);
            CP16(d,         g_gwh + (size_t)(nbase + row) * DIN + kbase + u * 8);
            CP16(d + 16384, g_gwl + (size_t)(nbase + row) * DIN + kbase + u * 8);
        }
        CP_COMMIT();
    };

    float acc[2][8][4];
#pragma unroll
    for (int mf = 0; mf < 2; ++mf)
#pragma unroll
        for (int nf = 0; nf < 8; ++nf)
#pragma unroll
            for (int j = 0; j < 4; ++j) acc[mf][nf][j] = 0.f;

    load_chunk(0);
    load_chunk(1);
    load_chunk(2);

    const int NCH = DIN / 32;
    for (int ch = 0; ch < NCH; ++ch) {
        CP_WAIT(2);
        __syncthreads();
        if (ch + 3 < NCH) load_chunk(ch + 3);
        else              CP_COMMIT();

        const uint32_t sb  = smb + (ch & 3) * GSTG;
        const uint32_t aHI = sb, aLO = sb + 8192, bHI = sb + 16384, bLO = sb + 32768;

#pragma unroll
        for (int ks = 0; ks < 2; ++ks) {
            const int k0 = ks * 16;
            uint32_t ahi[2][4], alo[2][4];
            {
                int r_ = (lane & 7) + ((lane >> 3) & 1) * 8;
                int au = (k0 >> 3) + (lane >> 4);
#pragma unroll
                for (int mf = 0; mf < 2; ++mf) {
                    int r = wm * 32 + mf * 16 + r_;
                    LDSM4(ahi[mf], aHI + sw32(r, au));
                    LDSM4(alo[mf], aLO + sw32(r, au));
                }
            }
#pragma unroll
            for (int g = 0; g < 2; ++g) {
                uint32_t bhi[4][2], blo[4][2];
                int n_ = (lane & 7) + (lane >> 4) * 8;
                int bu = (k0 >> 3) + ((lane >> 3) & 1);
#pragma unroll
                for (int nb = 0; nb < 2; ++nb) {
                    int n = wn * 64 + (g * 2 + nb) * 16 + n_;
                    uint32_t r4[4];
                    LDSM4(r4, bHI + sw32(n, bu));
                    bhi[2 * nb][0] = r4[0]; bhi[2 * nb][1] = r4[1];
                    bhi[2 * nb + 1][0] = r4[2]; bhi[2 * nb + 1][1] = r4[3];
                    LDSM4(r4, bLO + sw32(n, bu));
                    blo[2 * nb][0] = r4[0]; blo[2 * nb][1] = r4[1];
                    blo[2 * nb + 1][0] = r4[2]; blo[2 * nb + 1][1] = r4[3];
                }
#pragma unroll
                for (int mf = 0; mf < 2; ++mf)
#pragma unroll
                    for (int nf = 0; nf < 4; ++nf)
                        MMA16816H(acc[mf][g * 4 + nf], ahi[mf], bhi[nf]);
#pragma unroll
                for (int mf = 0; mf < 2; ++mf)
#pragma unroll
                    for (int nf = 0; nf < 4; ++nf)
                        MMA16816H(acc[mf][g * 4 + nf], alo[mf], bhi[nf]);
#pragma unroll
                for (int mf = 0; mf < 2; ++mf)
#pragma unroll
                    for (int nf = 0; nf < 4; ++nf)
                        MMA16816H(acc[mf][g * 4 + nf], ahi[mf], blo[nf]);
            }
        }
    }
    __syncthreads();   // mainloop done; stage smem reusable

    // ---- epilogue: relu(h+b) -> hi/lo fp16 chunks; gow planes -> smem ----
    const uint32_t HHI = smb;            // 64 KB: 8 chunk-blocks of 8 KB
    const uint32_t HLO = smb + 65536;    // 64 KB
    __half* gwHs = (__half*)(smp + 131072);             // [16][264]
    __half* gwLs = (__half*)(smp + 131072 + 16 * 264 * 2);

    for (int idx = tid; idx < 16 * 256; idx += 512) {
        int ee = idx >> 8, k = idx & 255;
        gwHs[ee * 264 + k] = g_gowTh[ee * NH + nbase + k];
        gwLs[ee * 264 + k] = g_gowTl[ee * NH + nbase + k];
    }

    const int grp = lane >> 2, t2 = (lane & 3) * 2;
#pragma unroll
    for (int mf = 0; mf < 2; ++mf)
#pragma unroll
        for (int nf = 0; nf < 8; ++nf) {
            const float* c = acc[mf][nf];
            int col = wn * 64 + nf * 8 + t2;
            int chunk_local = wn * 2 + (nf >> 2);
            int u = nf & 3;
#pragma unroll
            for (int h8 = 0; h8 < 2; ++h8) {
                int r = wm * 32 + mf * 16 + grp + h8 * 8;
                float v0 = fmaxf(c[h8 * 2]     + sbias[col], 0.f);
                float v1 = fmaxf(c[h8 * 2 + 1] + sbias[col + 1], 0.f);
                __half hh0 = __float2half_rn(v0), hh1 = __float2half_rn(v1);
                __half hl0 = __float2half_rn(v0 - __half2float(hh0));
                __half hl1 = __float2half_rn(v1 - __half2float(hh1));
                __half2 phi = __halves2half2(hh0, hh1);
                __half2 plo = __halves2half2(hl0, hl1);
                uint32_t off = chunk_local * 8192 + sw32(r, u) + t2 * 2;
                *(uint32_t*)(smp + off)         = *(uint32_t*)&phi;
                *(uint32_t*)(smp + 65536 + off) = *(uint32_t*)&plo;
            }
        }
    __syncthreads();

    // ---- logit MMA: warp -> (mt = wid>>1, nt = wid&1); C = 16 tok x 8 e ----
    {
        const int mt = wid >> 1, nt = wid & 1;
        float lc[4] = {0.f, 0.f, 0.f, 0.f};
        const int bn  = nt * 8 + (lane >> 2);
        const int bk0 = (lane & 3) * 2;
        const int r_  = mt * 16 + (lane & 7) + ((lane >> 3) & 1) * 8;
#pragma unroll
        for (int kc = 0; kc < 8; ++kc) {
#pragma unroll
            for (int ks = 0; ks < 2; ++ks) {
                const int k0 = ks * 16;
                const int au = (k0 >> 3) + (lane >> 4);
                uint32_t ahi[4], alo[4];
                LDSM4(ahi, HHI + kc * 8192 + sw32(r_, au));
                LDSM4(alo, HLO + kc * 8192 + sw32(r_, au));
                int kb = kc * 32 + k0 + bk0;
                uint32_t bhi[2], blo[2];
                bhi[0] = *(uint32_t*)&gwHs[bn * 264 + kb];
                bhi[1] = *(uint32_t*)&gwHs[bn * 264 + kb + 8];
                blo[0] = *(uint32_t*)&gwLs[bn * 264 + kb];
                blo[1] = *(uint32_t*)&gwLs[bn * 264 + kb + 8];
                MMA16816H(lc, ahi, bhi);
                MMA16816H(lc, alo, bhi);
                MMA16816H(lc, ahi, blo);
            }
        }
        int tokb = tile * 128 + mt * 16;
        int eidx = nt * 8 + t2;
        atomicAdd(&g_logits[(tokb + grp) * NE + eidx],         lc[0]);
        atomicAdd(&g_logits[(tokb + grp) * NE + eidx + 1],     lc[1]);
        atomicAdd(&g_logits[(tokb + grp + 8) * NE + eidx],     lc[2]);
        atomicAdd(&g_logits[(tokb + grp + 8) * NE + eidx + 1], lc[3]);
    }

    // ---- routing: last CTA of this tile does top-2 + softmax + append ----
    __threadfence();
    __syncthreads();
    if (tid == 0) s_flag = atomicAdd(&g_tilecnt[tile], 1);
    __syncthreads();
    if (s_flag == 1 && tid < 128) {
        int tok = tile * 128 + tid;
        float v0 = -1e30f, v1 = -1e30f;
        int i0 = 0, i1 = 0;
#pragma unroll
        for (int e = 0; e < NE; ++e) {
            float lg = __ldcg(&g_logits[tok * NE + e]);
            if (lg > v0)      { v1 = v0; i1 = i0; v0 = lg; i0 = e; }
            else if (lg > v1) { v1 = lg; i1 = e; }
        }
        float e1 = __expf(v1 - v0);
        float sden = 1.f + e1;
        int p0 = atomicAdd(&g_cnt[i0], 1);
        g_rtok[i0 * NTOK + p0]  = tok;
        g_rgate[i0 * NTOK + p0] = 1.f / sden;
        int p1 = atomicAdd(&g_cnt[i1], 1);
        g_rtok[i1 * NTOK + p1]  = tok;
        g_rgate[i1 * NTOK + p1] = e1 / sden;
    }
}

// ---------------------------------------------------------------------------
// expert_fused: one CTA per (expert, 128-token tile) runs all 3 layers.
// (byte-identical to round 14)
// ---------------------------------------------------------------------------
#define H1OFF 0
#define H2OFF 131072
#define BOFF  196608
#define EB    16384
#define SMEXP 229376

__global__ __launch_bounds__(512, 1) void expert_fused_kernel(
    const float* __restrict__ b1, const float* __restrict__ b2,
    const float* __restrict__ b3, float* __restrict__ outp)
{
    const int e    = blockIdx.y;
    const int tile = blockIdx.x;
    const int cnt  = g_cnt[e];
    if (tile * 128 >= cnt) return;
    const int m = min(128, cnt - tile * 128);

    extern __shared__ char smp[];
    const uint32_t smb = smem_u32(smp);
    __shared__ int   toks[128];
    __shared__ float gts[128];
    __shared__ float sbias[256];

    const int tid  = threadIdx.x;
    const int wid  = tid >> 5, lane = tid & 31;
    const int wm   = wid & 3,  wn   = wid >> 2;
    const int grp  = lane >> 2, t2 = (lane & 3) * 2;

    if (tid < 128) {
        int i = tile * 128 + tid;
        bool v = (i < cnt);
        toks[tid] = v ? g_rtok[e * NTOK + i] : 0;
        gts[tid]  = v ? g_rgate[e * NTOK + i] : 0.f;
    }
    __syncthreads();

    float acc[2][8][4];

    auto zero_acc = [&]() {
#pragma unroll
        for (int mf = 0; mf < 2; ++mf)
#pragma unroll
            for (int nf = 0; nf < 8; ++nf)
#pragma unroll
                for (int j = 0; j < 4; ++j) acc[mf][nf][j] = 0.f;
    };

    auto loadB = [&](const __half* Bp, int kstride, int ch) {
        const int kbase = ch * 32;
        const uint32_t sb = smb + BOFF + (ch & 1) * EB;
#pragma unroll
        for (int i = 0; i < 2; ++i) {
            int idx = tid + i * 512;
            int row = idx >> 2, u = idx & 3;
            CP16(sb + sw32(row, u), Bp + (size_t)row * kstride + kbase + u * 8);
        }
    };

    auto compute_chunk = [&](uint32_t aB, uint32_t bB) {
#pragma unroll
        for (int ks = 0; ks < 2; ++ks) {
            const int k0 = ks * 16;
            uint32_t af[2][4];
            {
                int r_ = (lane & 7) + ((lane >> 3) & 1) * 8;
                int au = (k0 >> 3) + (lane >> 4);
#pragma unroll
                for (int mf = 0; mf < 2; ++mf) {
                    int r = wm * 32 + mf * 16 + r_;
                    LDSM4(af[mf], aB + sw32(r, au));
                }
            }
#pragma unroll
            for (int g = 0; g < 2; ++g) {
                uint32_t bf[4][2];
                int n_ = (lane & 7) + (lane >> 4) * 8;
                int bu = (k0 >> 3) + ((lane >> 3) & 1);
#pragma unroll
                for (int nb = 0; nb < 2; ++nb) {
                    int n = wn * 64 + (g * 2 + nb) * 16 + n_;
                    uint32_t r4[4];
                    LDSM4(r4, bB + sw32(n, bu));
                    bf[2 * nb][0] = r4[0]; bf[2 * nb][1] = r4[1];
                    bf[2 * nb + 1][0] = r4[2]; bf[2 * nb + 1][1] = r4[3];
                }
#pragma unroll
                for (int mf = 0; mf < 2; ++mf)
#pragma unroll
                    for (int nf = 0; nf < 4; ++nf)
                        MMA16816H(acc[mf][g * 4 + nf], af[mf], bf[nf]);
            }
        }
    };

    auto run_phase = [&](const __half* Bp, int kstride, int NCH, auto abase,
                         bool prologue) {
        if (prologue) {
            loadB(Bp, kstride, 0); CP_COMMIT();
            loadB(Bp, kstride, 1); CP_COMMIT();
        }
        for (int ch = 0; ch < NCH; ++ch) {
            CP_WAIT(1);
            __syncthreads();
            compute_chunk(abase(ch), smb + BOFF + (ch & 1) * EB);
            __syncthreads();
            if (ch + 2 < NCH) loadB(Bp, kstride, ch + 2);
            CP_COMMIT();
        }
    };

    auto epi_h = [&](uint32_t hbase) {
#pragma unroll
        for (int mf = 0; mf < 2; ++mf)
#pragma unroll
            for (int nf = 0; nf < 8; ++nf) {
                const float* c = acc[mf][nf];
                int col = wn * 64 + nf * 8 + t2;
                int chunk_local = wn * 2 + (nf >> 2);
                int u = nf & 3;
#pragma unroll
                for (int h8 = 0; h8 < 2; ++h8) {
                    int r = wm * 32 + mf * 16 + grp + h8 * 8;
                    __half2 h = __floats2half2_rn(
                        fmaxf(c[h8 * 2]     + sbias[col], 0.f),
                        fmaxf(c[h8 * 2 + 1] + sbias[col + 1], 0.f));
                    *(uint32_t*)(smp + hbase + chunk_local * 8192 +
                                 sw32(r, u) + t2 * 2) = *(uint32_t*)&h;
                }
            }
    };

    const __half* w1p = g_w1T + (size_t)e * NH * DIN;
    const __half* w2p = g_w2T + (size_t)e * NH * NH;
    const __half* w3p = g_w3T + (size_t)e * DOUT * NH;

    // ---- L1 ----
    {
#pragma unroll
        for (int c = 0; c < 8; ++c) {
            int row = tid >> 2, u = tid & 3;
            CP16(smb + H2OFF + c * 8192 + sw32(row, u),
                 g_xh + (size_t)toks[row] * DIN + c * 32 + u * 8);
        }
        loadB(w1p, DIN, 0); CP_COMMIT();
        loadB(w1p, DIN, 1); CP_COMMIT();

        auto abaseX = [&](int ch) { return smb + H2OFF + ch * 8192; };
#pragma unroll
        for (int half = 0; half < 2; ++half) {
            if (tid < 256) sbias[tid] = b1[e * NH + half * 256 + tid];
            zero_acc();
            run_phase(w1p + (size_t)half * 256 * DIN, DIN, DIN / 32, abaseX,
                      half == 1);
            epi_h(H1OFF + half * 65536);
            __syncthreads();
        }
    }

    // ---- L2 ----
    {
        auto abaseH1 = [&](int ch) { return smb + H1OFF + ch * 8192; };
#pragma unroll
        for (int half = 0; half < 2; ++half) {
            if (tid < 256) sbias[tid] = b2[e * NH + half * 256 + tid];
            zero_acc();
            run_phase(w2p + (size_t)half * 256 * NH, NH, NH / 32, abaseH1, true);
            epi_h(half == 0 ? H2OFF : H1OFF);
            __syncthreads();
        }
    }

    // ---- L3 ----
    {
        if (tid < 256) sbias[tid] = b3[e * DOUT + tid];
        zero_acc();
        auto abaseH2 = [&](int ch) {
            return (ch < 8) ? (smb + H2OFF + ch * 8192)
                            : (smb + H1OFF + (ch - 8) * 8192);
        };
        run_phase(w3p, NH, NH / 32, abaseH2, true);

#pragma unroll
        for (int mf = 0; mf < 2; ++mf)
#pragma unroll
            for (int nf = 0; nf < 8; ++nf) {
                const float* c = acc[mf][nf];
                const int col = wn * 64 + nf * 8 + t2;
#pragma unroll
                for (int h8 = 0; h8 < 2; ++h8) {
                    const int r = wm * 32 + mf * 16 + grp + h8 * 8;
                    if (r < m) {
                        float g = gts[r];
                        float* orow = outp + (size_t)toks[r] * DOUT + col;
                        atomicAdd(orow,     g * (c[h8 * 2]     + sbias[col]));
                        atomicAdd(orow + 1, g * (c[h8 * 2 + 1] + sbias[col + 1]));
                    }
                }
            }
    }
}

// ---------------------------------------------------------------------------
extern "C" void kernel_launch(void* const* d_in, const int* in_sizes, int n_in,
                              void* d_out, int out_size)
{
    const float* x   = (const float*)d_in[0];
    const float* gw  = (const float*)d_in[1];
    const float* gb  = (const float*)d_in[2];
    const float* gow = (const float*)d_in[3];
    const float* gob = (const float*)d_in[4];
    const float* w1  = (const float*)d_in[5];
    const float* b1  = (const float*)d_in[6];
    const float* w2  = (const float*)d_in[7];
    const float* b2  = (const float*)d_in[8];
    const float* w3  = (const float*)d_in[9];
    const float* b3  = (const float*)d_in[10];
    float* out = (float*)d_out;

    static cudaStream_t s_side = nullptr;
    static cudaEvent_t  s_evF = nullptr, s_evJ = nullptr;
    if (!s_side) {
        cudaStreamCreateWithFlags(&s_side, cudaStreamNonBlocking);
        cudaEventCreateWithFlags(&s_evF, cudaEventDisableTiming);
        cudaEventCreateWithFlags(&s_evJ, cudaEventDisableTiming);
    }

    const int smg = 4 * GSTG;    // 192 KB
    cudaFuncSetAttribute(gate_mma_kernel, cudaFuncAttributeMaxDynamicSharedMemorySize, smg);
    cudaFuncSetAttribute(expert_fused_kernel, cudaFuncAttributeMaxDynamicSharedMemorySize, SMEXP);

    // ---- fork ----
    cudaEventRecord(s_evF, 0);
    cudaStreamWaitEvent(s_side, s_evF, 0);

    prep_gate_kernel<<<2690, 256>>>(x, gw, gob, gow);            // #1 (main)
    cudaMemsetAsync(out, 0, (size_t)NTOK * DOUT * sizeof(float), s_side);
    prep_expert_kernel<<<8192, 256, 0, s_side>>>(w1, w2, w3);    // #2 (side)
    gate_mma_kernel<<<dim3(64, 2), 512, smg>>>(gb);              // #3 (main)

    // ---- join ----
    cudaEventRecord(s_evJ, s_side);
    cudaStreamWaitEvent(0, s_evJ, 0);

    expert_fused_kernel<<<dim3(64, NE), 512, SMEXP>>>(b1, b2, b3, out);  // #4 -> ncu
}

// round 16
// speedup vs baseline: 1.0176x; 1.0176x over previous
#include <cuda_runtime.h>
#include <cuda_bf16.h>
#include <cuda_fp16.h>
#include <cstdint>

#define NTOK 8192
#define DIN  256
#define DOUT 256
#define NE   16
#define NH   512

// ---------------------------------------------------------------------------
// Device scratch
// ---------------------------------------------------------------------------
__device__ int   g_cnt[NE];
__device__ int   g_tilecnt[64];
__device__ int   g_rtok[NE * NTOK];
__device__ float g_rgate[NE * NTOK];
__device__ float g_logits[NTOK * NE];

__device__ __half g_xh[NTOK * DIN], g_xlo[NTOK * DIN];
__device__ __half g_gwh[NH * DIN],  g_gwl[NH * DIN];    // gate_w planes [n=512][k=256]
__device__ __half g_w1T[NE * NH * DIN];     // [e][n=512][k=256]
__device__ __half g_w2T[NE * NH * NH];      // [e][512][512]
__device__ __half g_w3T[NE * DOUT * NH];    // [e][256][512]

// ---------------------------------------------------------------------------
// PTX helpers (compute_103-safe: cp.async + ldmatrix + mma.sync only)
// ---------------------------------------------------------------------------
__device__ __forceinline__ uint32_t smem_u32(const void* p) {
    uint32_t a;
    asm("{ .reg .u64 t; cvta.to.shared.u64 t, %1; cvt.u32.u64 %0, t; }" : "=r"(a) : "l"(p));
    return a;
}
#define CP16(dst, src) \
    asm volatile("cp.async.cg.shared.global [%0], [%1], 16;" :: "r"(dst), "l"(src) : "memory")
#define CP_COMMIT() asm volatile("cp.async.commit_group;" ::: "memory")
#define CP_WAIT(n)  asm volatile("cp.async.wait_group %0;" :: "n"(n) : "memory")

#define LDSM4(r, addr) \
    asm volatile("ldmatrix.sync.aligned.m8n8.x4.shared.b16 {%0,%1,%2,%3}, [%4];" \
        : "=r"((r)[0]), "=r"((r)[1]), "=r"((r)[2]), "=r"((r)[3]) : "r"(addr))

#define MMA16816H(c, a, b) \
    asm volatile("mma.sync.aligned.m16n8k16.row.col.f32.f16.f16.f32 " \
        "{%0,%1,%2,%3}, {%4,%5,%6,%7}, {%8,%9}, {%0,%1,%2,%3};" \
        : "+f"((c)[0]), "+f"((c)[1]), "+f"((c)[2]), "+f"((c)[3]) \
        : "r"((a)[0]), "r"((a)[1]), "r"((a)[2]), "r"((a)[3]), "r"((b)[0]), "r"((b)[1]))

// Packed fp32x2 helpers (logit epilogue)
#define FMA2(d, a, b) asm("fma.rn.f32x2 %0, %1, %2, %0;" : "+l"(d) : "l"(a), "l"(b))
#define DUP2(d, s)    asm("mov.b64 %0, {%1, %1};" : "=l"(d) : "f"(s))
#define UNPK(lo, hi, s) asm("mov.b64 {%0, %1}, %2;" : "=f"(lo), "=f"(hi) : "l"(s))

// Pair-packed 64B-row swizzle: logical (row, k-unit) in 128B phys rows.
__device__ __forceinline__ uint32_t sw32(int row, int u) {
    return (uint32_t)((row >> 1) * 128 +
                      (((((row & 1) << 2) + u) ^ ((row >> 1) & 7)) << 4));
}

// ---------------------------------------------------------------------------
// prep_gate: x -> hi/lo fp16; gate_w -> transposed hi/lo; logits <- bias;
// zero g_cnt / g_tilecnt.
//   [0,2048) x split | [2048,2176) gw tiles | [2176,2688) logits | 2688 zero
// ---------------------------------------------------------------------------
__global__ __launch_bounds__(256) void prep_gate_kernel(
    const float* __restrict__ x, const float* __restrict__ gw,
    const float* __restrict__ gob)
{
    const int bid = blockIdx.x;
    const int tid = threadIdx.x;

    if (bid < 2048) {
        int base = bid * 512 + tid;
#pragma unroll
        for (int j = 0; j < 2; ++j) {
            int i = base + j * 256;
            float2 v = ((const float2*)x)[i];
            __half h0 = __float2half_rn(v.x), h1 = __float2half_rn(v.y);
            __half l0 = __float2half_rn(v.x - __half2float(h0));
            __half l1 = __float2half_rn(v.y - __half2float(h1));
            __half2 hh = __halves2half2(h0, h1), ll = __halves2half2(l0, l1);
            ((uint32_t*)g_xh)[i]  = *(uint32_t*)&hh;
            ((uint32_t*)g_xlo)[i] = *(uint32_t*)&ll;
        }
        return;
    }
    if (bid < 2176) {
        __shared__ float t[32][33];
        const int tx = tid & 31, ty = tid >> 5;
        int r = bid - 2048;
        int n0 = (r & 15) * 32, k0 = (r >> 4) * 32;
#pragma unroll
        for (int i = 0; i < 4; ++i)
            t[ty + 8 * i][tx] = gw[(long)(k0 + ty + 8 * i) * NH + n0 + tx];
        __syncthreads();
#pragma unroll
        for (int i = 0; i < 4; ++i) {
            float v = t[tx][ty + 8 * i];
            __half h = __float2half_rn(v);
            __half l = __float2half_rn(v - __half2float(h));
            size_t idx = (size_t)(n0 + ty + 8 * i) * DIN + k0 + tx;
            g_gwh[idx] = h;
            g_gwl[idx] = l;
        }
        return;
    }
    if (bid < 2688) {
        int i = (bid - 2176) * 256 + tid;
        g_logits[i] = gob[i & 15];
        return;
    }
    if (tid < NE) g_cnt[tid] = 0;
    if (tid < 64) g_tilecnt[tid] = 0;
}

// ---------------------------------------------------------------------------
// prep_expert: 3 weight transposes -> single fp16 planes.
// ---------------------------------------------------------------------------
__global__ __launch_bounds__(256) void prep_expert_kernel(
    const float* __restrict__ w1, const float* __restrict__ w2,
    const float* __restrict__ w3)
{
    const int bid = blockIdx.x;
    const int tid = threadIdx.x;
    __shared__ float t[32][33];
    const int tx = tid & 31, ty = tid >> 5;

    const float* src; long rs; int K, N, e, n0, k0;
    __half* dh;
    if (bid < 2048) {                    // w1
        int l = bid;
        e = l >> 7; int r = l & 127;
        n0 = (r & 15) * 32; k0 = (r >> 4) * 32;
        src = w1 + e * NH; rs = (long)NE * NH; K = DIN; N = NH;
        dh = g_w1T;
    } else if (bid < 6144) {             // w2
        int l = bid - 2048;
        e = l >> 8; int r = l & 255;
        n0 = (r & 15) * 32; k0 = (r >> 4) * 32;
        src = w2 + e * NH; rs = (long)NE * NH; K = NH; N = NH;
        dh = g_w2T;
    } else {                             // w3
        int l = bid - 6144;
        e = l >> 7; int r = l & 127;
        n0 = (r & 7) * 32; k0 = (r >> 3) * 32;
        src = w3 + e * DOUT; rs = (long)NE * DOUT; K = NH; N = DOUT;
        dh = g_w3T;
    }
    dh += (size_t)e * N * K;

#pragma unroll
    for (int i = 0; i < 4; ++i)
        t[ty + 8 * i][tx] = src[(long)(k0 + ty + 8 * i) * rs + n0 + tx];
    __syncthreads();
#pragma unroll
    for (int i = 0; i < 4; ++i)
        dh[(size_t)(n0 + ty + 8 * i) * K + k0 + tx] = __float2half_rn(t[tx][ty + 8 * i]);
}

// ---------------------------------------------------------------------------
// gate_mma: 3-product split-fp16 hidden GEMM + partial logits (FMA2-packed)
// + (last CTA of each tile) routing. Grid (64, 2).
// ---------------------------------------------------------------------------
#define GSTG 49152
#define HSP  264
#define GPAD 20

__global__ __launch_bounds__(512, 1) void gate_mma_kernel(
    const float* __restrict__ gb, const float* __restrict__ gow)
{
    const int tile  = blockIdx.x;
    const int nbase = blockIdx.y * 256;

    extern __shared__ char smp[];
    const uint32_t smb = smem_u32(smp);
    __shared__ float sbias[256];
    __shared__ int   s_flag;

    const int tid  = threadIdx.x;
    const int wid  = tid >> 5, lane = tid & 31;
    const int wm   = wid & 3,  wn   = wid >> 2;

    if (tid < 256) sbias[tid] = gb[nbase + tid];
    __syncthreads();

    auto load_chunk = [&](int ch) {
        const int kbase = ch * 32;
        const uint32_t sb = smb + (ch & 3) * GSTG;
        {
            int row = tid >> 2, u = tid & 3;
            uint32_t d = sb + sw32(row, u);
            long arow = (long)tile * 128 + row;
            CP16(d,        g_xh  + arow * DIN + kbase + u * 8);
            CP16(d + 8192, g_xlo + arow * DIN + kbase + u * 8);
        }
#pragma unroll
        for (int i = 0; i < 2; ++i) {
            int idx = tid + i * 512;
            int row = idx >> 2, u = idx & 3;
            uint32_t d = sb + 16384 + sw32(row, u);
            CP16(d,         g_gwh + (size_t)(nbase + row) * DIN + kbase + u * 8);
            CP16(d + 16384, g_gwl + (size_t)(nbase + row) * DIN + kbase + u * 8);
        }
        CP_COMMIT();
    };

    float acc[2][8][4];
#pragma unroll
    for (int mf = 0; mf < 2; ++mf)
#pragma unroll
        for (int nf = 0; nf < 8; ++nf)
#pragma unroll
            for (int j = 0; j < 4; ++j) acc[mf][nf][j] = 0.f;

    load_chunk(0);
    load_chunk(1);
    load_chunk(2);

    const int NCH = DIN / 32;
    for (int ch = 0; ch < NCH; ++ch) {
        CP_WAIT(2);
        __syncthreads();
        if (ch + 3 < NCH) load_chunk(ch + 3);
        else              CP_COMMIT();

        const uint32_t sb  = smb + (ch & 3) * GSTG;
        const uint32_t aHI = sb, aLO = sb + 8192, bHI = sb + 16384, bLO = sb + 32768;

#pragma unroll
        for (int ks = 0; ks < 2; ++ks) {
            const int k0 = ks * 16;
            uint32_t ahi[2][4], alo[2][4];
            {
                int r_ = (lane & 7) + ((lane >> 3) & 1) * 8;
                int au = (k0 >> 3) + (lane >> 4);
#pragma unroll
                for (int mf = 0; mf < 2; ++mf) {
                    int r = wm * 32 + mf * 16 + r_;
                    LDSM4(ahi[mf], aHI + sw32(r, au));
                    LDSM4(alo[mf], aLO + sw32(r, au));
                }
            }
#pragma unroll
            for (int g = 0; g < 2; ++g) {
                uint32_t bhi[4][2], blo[4][2];
                int n_ = (lane & 7) + (lane >> 4) * 8;
                int bu = (k0 >> 3) + ((lane >> 3) & 1);
#pragma unroll
                for (int nb = 0; nb < 2; ++nb) {
                    int n = wn * 64 + (g * 2 + nb) * 16 + n_;
                    uint32_t r4[4];
                    LDSM4(r4, bHI + sw32(n, bu));
                    bhi[2 * nb][0] = r4[0]; bhi[2 * nb][1] = r4[1];
                    bhi[2 * nb + 1][0] = r4[2]; bhi[2 * nb + 1][1] = r4[3];
                    LDSM4(r4, bLO + sw32(n, bu));
                    blo[2 * nb][0] = r4[0]; blo[2 * nb][1] = r4[1];
                    blo[2 * nb + 1][0] = r4[2]; blo[2 * nb + 1][1] = r4[3];
                }
#pragma unroll
                for (int mf = 0; mf < 2; ++mf)
#pragma unroll
                    for (int nf = 0; nf < 4; ++nf)
                        MMA16816H(acc[mf][g * 4 + nf], ahi[mf], bhi[nf]);
#pragma unroll
                for (int mf = 0; mf < 2; ++mf)
#pragma unroll
                    for (int nf = 0; nf < 4; ++nf)
                        MMA16816H(acc[mf][g * 4 + nf], alo[mf], bhi[nf]);
#pragma unroll
                for (int mf = 0; mf < 2; ++mf)
#pragma unroll
                    for (int nf = 0; nf < 4; ++nf)
                        MMA16816H(acc[mf][g * 4 + nf], ahi[mf], blo[nf]);
            }
        }
    }
    __syncthreads();

    // ---- epilogue: partial logits (FMA2-packed across experts) ----
    float* Hsm  = (float*)smp;            // [64][HSP]
    float* gowS = Hsm + 64 * HSP;         // [256][GPAD]; rows 80B -> 16B aligned
    for (int idx = tid; idx < 256 * NE; idx += 512) {
        int r = idx >> 4, c = idx & 15;
        gowS[r * GPAD + c] = gow[(nbase + r) * NE + c];
    }

    const int grp = lane >> 2, t2 = (lane & 3) * 2;
#pragma unroll
    for (int hp = 0; hp < 2; ++hp) {
        if (hp == 1) __syncthreads();
        if ((wm >> 1) == hp) {
            int rbase = (wm & 1) * 32;
#pragma unroll
            for (int mf = 0; mf < 2; ++mf)
#pragma unroll
                for (int nf = 0; nf < 8; ++nf) {
                    const float* c = acc[mf][nf];
                    int col = wn * 64 + nf * 8 + t2;
#pragma unroll
                    for (int h8 = 0; h8 < 2; ++h8) {
                        int lr = rbase + mf * 16 + grp + h8 * 8;
                        Hsm[lr * HSP + col]     = fmaxf(c[h8 * 2] + sbias[col], 0.f);
                        Hsm[lr * HSP + col + 1] = fmaxf(c[h8 * 2 + 1] + sbias[col + 1], 0.f);
                    }
                }
        }
        __syncthreads();

        const int t = tid >> 3, s = tid & 7;
        unsigned long long lacc[8];
#pragma unroll
        for (int p = 0; p < 8; ++p) DUP2(lacc[p], 0.f);
#pragma unroll 4
        for (int i = 0; i < 32; ++i) {
            int rk = s + 8 * i;
            float v = Hsm[t * HSP + rk];
            unsigned long long vv;
            DUP2(vv, v);
            const ulonglong2* gp = (const ulonglong2*)(gowS + rk * GPAD);
            ulonglong2 g0 = gp[0], g1 = gp[1], g2 = gp[2], g3 = gp[3];
            FMA2(lacc[0], g0.x, vv);  FMA2(lacc[1], g0.y, vv);
            FMA2(lacc[2], g1.x, vv);  FMA2(lacc[3], g1.y, vv);
            FMA2(lacc[4], g2.x, vv);  FMA2(lacc[5], g2.y, vv);
            FMA2(lacc[6], g3.x, vv);  FMA2(lacc[7], g3.y, vv);
        }
        float l[NE];
#pragma unroll
        for (int p = 0; p < 8; ++p) UNPK(l[2 * p], l[2 * p + 1], lacc[p]);
#pragma unroll
        for (int m2 = 1; m2 < 8; m2 <<= 1)
#pragma unroll
            for (int e = 0; e < NE; ++e)
                l[e] += __shfl_xor_sync(0xffffffffu, l[e], m2);

        int tok = tile * 128 + hp * 64 + t;
        atomicAdd(&g_logits[tok * NE + 2 * s],     l[2 * s]);
        atomicAdd(&g_logits[tok * NE + 2 * s + 1], l[2 * s + 1]);
    }

    // ---- routing: last CTA of this tile does top-2 + softmax + append ----
    __threadfence();
    __syncthreads();
    if (tid == 0) s_flag = atomicAdd(&g_tilecnt[tile], 1);
    __syncthreads();
    if (s_flag == 1 && tid < 128) {
        int tok = tile * 128 + tid;
        float v0 = -1e30f, v1 = -1e30f;
        int i0 = 0, i1 = 0;
#pragma unroll
        for (int e = 0; e < NE; ++e) {
            float lg = __ldcg(&g_logits[tok * NE + e]);
            if (lg > v0)      { v1 = v0; i1 = i0; v0 = lg; i0 = e; }
            else if (lg > v1) { v1 = lg; i1 = e; }
        }
        float e1 = __expf(v1 - v0);
        float sden = 1.f + e1;
        int p0 = atomicAdd(&g_cnt[i0], 1);
        g_rtok[i0 * NTOK + p0]  = tok;
        g_rgate[i0 * NTOK + p0] = 1.f / sden;
        int p1 = atomicAdd(&g_cnt[i1], 1);
        g_rtok[i1 * NTOK + p1]  = tok;
        g_rgate[i1 * NTOK + p1] = e1 / sden;
    }
}

// ---------------------------------------------------------------------------
// expert_fused: one CTA per (expert, 128-token tile) runs all 3 layers.
// (byte-identical to round 14)
// ---------------------------------------------------------------------------
#define H1OFF 0
#define H2OFF 131072
#define BOFF  196608
#define EB    16384
#define SMEXP 229376

__global__ __launch_bounds__(512, 1) void expert_fused_kernel(
    const float* __restrict__ b1, const float* __restrict__ b2,
    const float* __restrict__ b3, float* __restrict__ outp)
{
    const int e    = blockIdx.y;
    const int tile = blockIdx.x;
    const int cnt  = g_cnt[e];
    if (tile * 128 >= cnt) return;
    const int m = min(128, cnt - tile * 128);

    extern __shared__ char smp[];
    const uint32_t smb = smem_u32(smp);
    __shared__ int   toks[128];
    __shared__ float gts[128];
    __shared__ float sbias[256];

    const int tid  = threadIdx.x;
    const int wid  = tid >> 5, lane = tid & 31;
    const int wm   = wid & 3,  wn   = wid >> 2;
    const int grp  = lane >> 2, t2 = (lane & 3) * 2;

    if (tid < 128) {
        int i = tile * 128 + tid;
        bool v = (i < cnt);
        toks[tid] = v ? g_rtok[e * NTOK + i] : 0;
        gts[tid]  = v ? g_rgate[e * NTOK + i] : 0.f;
    }
    __syncthreads();

    float acc[2][8][4];

    auto zero_acc = [&]() {
#pragma unroll
        for (int mf = 0; mf < 2; ++mf)
#pragma unroll
            for (int nf = 0; nf < 8; ++nf)
#pragma unroll
                for (int j = 0; j < 4; ++j) acc[mf][nf][j] = 0.f;
    };

    auto loadB = [&](const __half* Bp, int kstride, int ch) {
        const int kbase = ch * 32;
        const uint32_t sb = smb + BOFF + (ch & 1) * EB;
#pragma unroll
        for (int i = 0; i < 2; ++i) {
            int idx = tid + i * 512;
            int row = idx >> 2, u = idx & 3;
            CP16(sb + sw32(row, u), Bp + (size_t)row * kstride + kbase + u * 8);
        }
    };

    auto compute_chunk = [&](uint32_t aB, uint32_t bB) {
#pragma unroll
        for (int ks = 0; ks < 2; ++ks) {
            const int k0 = ks * 16;
            uint32_t af[2][4];
            {
                int r_ = (lane & 7) + ((lane >> 3) & 1) * 8;
                int au = (k0 >> 3) + (lane >> 4);
#pragma unroll
                for (int mf = 0; mf < 2; ++mf) {
                    int r = wm * 32 + mf * 16 + r_;
                    LDSM4(af[mf], aB + sw32(r, au));
                }
            }
#pragma unroll
            for (int g = 0; g < 2; ++g) {
                uint32_t bf[4][2];
                int n_ = (lane & 7) + (lane >> 4) * 8;
                int bu = (k0 >> 3) + ((lane >> 3) & 1);
#pragma unroll
                for (int nb = 0; nb < 2; ++nb) {
                    int n = wn * 64 + (g * 2 + nb) * 16 + n_;
                    uint32_t r4[4];
                    LDSM4(r4, bB + sw32(n, bu));
                    bf[2 * nb][0] = r4[0]; bf[2 * nb][1] = r4[1];
                    bf[2 * nb + 1][0] = r4[2]; bf[2 * nb + 1][1] = r4[3];
                }
#pragma unroll
                for (int mf = 0; mf < 2; ++mf)
#pragma unroll
                    for (int nf = 0; nf < 4; ++nf)
                        MMA16816H(acc[mf][g * 4 + nf], af[mf], bf[nf]);
            }
        }
    };

    auto run_phase = [&](const __half* Bp, int kstride, int NCH, auto abase,
                         bool prologue) {
        if (prologue) {
            loadB(Bp, kstride, 0); CP_COMMIT();
            loadB(Bp, kstride, 1); CP_COMMIT();
        }
        for (int ch = 0; ch < NCH; ++ch) {
            CP_WAIT(1);
            __syncthreads();
            compute_chunk(abase(ch), smb + BOFF + (ch & 1) * EB);
            __syncthreads();
            if (ch + 2 < NCH) loadB(Bp, kstride, ch + 2);
            CP_COMMIT();
        }
    };

    auto epi_h = [&](uint32_t hbase) {
#pragma unroll
        for (int mf = 0; mf < 2; ++mf)
#pragma unroll
            for (int nf = 0; nf < 8; ++nf) {
                const float* c = acc[mf][nf];
                int col = wn * 64 + nf * 8 + t2;
                int chunk_local = wn * 2 + (nf >> 2);
                int u = nf & 3;
#pragma unroll
                for (int h8 = 0; h8 < 2; ++h8) {
                    int r = wm * 32 + mf * 16 + grp + h8 * 8;
                    __half2 h = __floats2half2_rn(
                        fmaxf(c[h8 * 2]     + sbias[col], 0.f),
                        fmaxf(c[h8 * 2 + 1] + sbias[col + 1], 0.f));
                    *(uint32_t*)(smp + hbase + chunk_local * 8192 +
                                 sw32(r, u) + t2 * 2) = *(uint32_t*)&h;
                }
            }
    };

    const __half* w1p = g_w1T + (size_t)e * NH * DIN;
    const __half* w2p = g_w2T + (size_t)e * NH * NH;
    const __half* w3p = g_w3T + (size_t)e * DOUT * NH;

    // ---- L1 ----
    {
#pragma unroll
        for (int c = 0; c < 8; ++c) {
            int row = tid >> 2, u = tid & 3;
            CP16(smb + H2OFF + c * 8192 + sw32(row, u),
                 g_xh + (size_t)toks[row] * DIN + c * 32 + u * 8);
        }
        loadB(w1p, DIN, 0); CP_COMMIT();
        loadB(w1p, DIN, 1); CP_COMMIT();

        auto abaseX = [&](int ch) { return smb + H2OFF + ch * 8192; };
#pragma unroll
        for (int half = 0; half < 2; ++half) {
            if (tid < 256) sbias[tid] = b1[e * NH + half * 256 + tid];
            zero_acc();
            run_phase(w1p + (size_t)half * 256 * DIN, DIN, DIN / 32, abaseX,
                      half == 1);
            epi_h(H1OFF + half * 65536);
            __syncthreads();
        }
    }

    // ---- L2 ----
    {
        auto abaseH1 = [&](int ch) { return smb + H1OFF + ch * 8192; };
#pragma unroll
        for (int half = 0; half < 2; ++half) {
            if (tid < 256) sbias[tid] = b2[e * NH + half * 256 + tid];
            zero_acc();
            run_phase(w2p + (size_t)half * 256 * NH, NH, NH / 32, abaseH1, true);
            epi_h(half == 0 ? H2OFF : H1OFF);
            __syncthreads();
        }
    }

    // ---- L3 ----
    {
        if (tid < 256) sbias[tid] = b3[e * DOUT + tid];
        zero_acc();
        auto abaseH2 = [&](int ch) {
            return (ch < 8) ? (smb + H2OFF + ch * 8192)
                            : (smb + H1OFF + (ch - 8) * 8192);
        };
        run_phase(w3p, NH, NH / 32, abaseH2, true);

#pragma unroll
        for (int mf = 0; mf < 2; ++mf)
#pragma unroll
            for (int nf = 0; nf < 8; ++nf) {
                const float* c = acc[mf][nf];
                const int col = wn * 64 + nf * 8 + t2;
#pragma unroll
                for (int h8 = 0; h8 < 2; ++h8) {
                    const int r = wm * 32 + mf * 16 + grp + h8 * 8;
                    if (r < m) {
                        float g = gts[r];
                        float* orow = outp + (size_t)toks[r] * DOUT + col;
                        atomicAdd(orow,     g * (c[h8 * 2]     + sbias[col]));
                        atomicAdd(orow + 1, g * (c[h8 * 2 + 1] + sbias[col + 1]));
                    }
                }
            }
    }
}

// ---------------------------------------------------------------------------
extern "C" void kernel_launch(void* const* d_in, const int* in_sizes, int n_in,
                              void* d_out, int out_size)
{
    const float* x   = (const float*)d_in[0];
    const float* gw  = (const float*)d_in[1];
    const float* gb  = (const float*)d_in[2];
    const float* gow = (const float*)d_in[3];
    const float* gob = (const float*)d_in[4];
    const float* w1  = (const float*)d_in[5];
    const float* b1  = (const float*)d_in[6];
    const float* w2  = (const float*)d_in[7];
    const float* b2  = (const float*)d_in[8];
    const float* w3  = (const float*)d_in[9];
    const float* b3  = (const float*)d_in[10];
    float* out = (float*)d_out;

    static cudaStream_t s_side = nullptr;
    static cudaEvent_t  s_evF = nullptr, s_evJ = nullptr;
    if (!s_side) {
        cudaStreamCreateWithFlags(&s_side, cudaStreamNonBlocking);
        cudaEventCreateWithFlags(&s_evF, cudaEventDisableTiming);
        cudaEventCreateWithFlags(&s_evJ, cudaEventDisableTiming);
    }

    const int smg = 4 * GSTG;    // 192 KB
    cudaFuncSetAttribute(gate_mma_kernel, cudaFuncAttributeMaxDynamicSharedMemorySize, smg);
    cudaFuncSetAttribute(expert_fused_kernel, cudaFuncAttributeMaxDynamicSharedMemorySize, SMEXP);

    // ---- fork ----
    cudaEventRecord(s_evF, 0);
    cudaStreamWaitEvent(s_side, s_evF, 0);

    prep_gate_kernel<<<2689, 256>>>(x, gw, gob);                 // #1 (main)
    cudaMemsetAsync(out, 0, (size_t)NTOK * DOUT * sizeof(float), s_side);
    prep_expert_kernel<<<8192, 256, 0, s_side>>>(w1, w2, w3);    // #2 (side)
    gate_mma_kernel<<<dim3(64, 2), 512, smg>>>(gb, gow);         // #3 (main)

    // ---- join ----
    cudaEventRecord(s_evJ, s_side);
    cudaStreamWaitEvent(0, s_evJ, 0);

    expert_fused_kernel<<<dim3(64, NE), 512, SMEXP>>>(b1, b2, b3, out);  // #4 -> ncu
}

// round 17
// speedup vs baseline: 1.0181x; 1.0005x over previous
#include <cuda_runtime.h>
#include <cuda_bf16.h>
#include <cuda_fp16.h>
#include <cstdint>

#define NTOK 8192
#define DIN  256
#define DOUT 256
#define NE   16
#define NH   512

// ---------------------------------------------------------------------------
// Device scratch
// ---------------------------------------------------------------------------
__device__ int   g_cnt[NE];
__device__ int   g_tilecnt[64];
__device__ int   g_rtok[NE * NTOK];
__device__ float g_rgate[NE * NTOK];
__device__ float g_logits[NTOK * NE];

__device__ __half g_xh[NTOK * DIN];                    // written by gate_mma
__device__ __half g_gwh[NH * DIN],  g_gwl[NH * DIN];   // gate_w planes [n=512][k=256]
__device__ __half g_w1T[NE * NH * DIN];     // [e][n=512][k=256]
__device__ __half g_w2T[NE * NH * NH];      // [e][512][512]
__device__ __half g_w3T[NE * DOUT * NH];    // [e][256][512]

// ---------------------------------------------------------------------------
// PTX helpers (compute_103-safe: cp.async + ldmatrix + mma.sync only)
// ---------------------------------------------------------------------------
__device__ __forceinline__ uint32_t smem_u32(const void* p) {
    uint32_t a;
    asm("{ .reg .u64 t; cvta.to.shared.u64 t, %1; cvt.u32.u64 %0, t; }" : "=r"(a) : "l"(p));
    return a;
}
#define CP16(dst, src) \
    asm volatile("cp.async.cg.shared.global [%0], [%1], 16;" :: "r"(dst), "l"(src) : "memory")
#define CP_COMMIT() asm volatile("cp.async.commit_group;" ::: "memory")
#define CP_WAIT(n)  asm volatile("cp.async.wait_group %0;" :: "n"(n) : "memory")

#define LDSM4(r, addr) \
    asm volatile("ldmatrix.sync.aligned.m8n8.x4.shared.b16 {%0,%1,%2,%3}, [%4];" \
        : "=r"((r)[0]), "=r"((r)[1]), "=r"((r)[2]), "=r"((r)[3]) : "r"(addr))

#define MMA16816H(c, a, b) \
    asm volatile("mma.sync.aligned.m16n8k16.row.col.f32.f16.f16.f32 " \
        "{%0,%1,%2,%3}, {%4,%5,%6,%7}, {%8,%9}, {%0,%1,%2,%3};" \
        : "+f"((c)[0]), "+f"((c)[1]), "+f"((c)[2]), "+f"((c)[3]) \
        : "r"((a)[0]), "r"((a)[1]), "r"((a)[2]), "r"((a)[3]), "r"((b)[0]), "r"((b)[1]))

// Packed fp32x2 helpers (logit epilogue)
#define FMA2(d, a, b) asm("fma.rn.f32x2 %0, %1, %2, %0;" : "+l"(d) : "l"(a), "l"(b))
#define DUP2(d, s)    asm("mov.b64 %0, {%1, %1};" : "=l"(d) : "f"(s))
#define UNPK(lo, hi, s) asm("mov.b64 {%0, %1}, %2;" : "=f"(lo), "=f"(hi) : "l"(s))

// Pair-packed 64B-row swizzle: logical (row, k-unit) in 128B phys rows.
__device__ __forceinline__ uint32_t sw32(int row, int u) {
    return (uint32_t)((row >> 1) * 128 +
                      (((((row & 1) << 2) + u) ^ ((row >> 1) & 7)) << 4));
}

// ---------------------------------------------------------------------------
// prep_gate (small): gate_w -> transposed hi/lo planes; logits <- bias; zero.
//   [0,128) gw tiles | [128,640) logits init | 640 zero counters
// ---------------------------------------------------------------------------
__global__ __launch_bounds__(256) void prep_gate_kernel(
    const float* __restrict__ gw, const float* __restrict__ gob)
{
    const int bid = blockIdx.x;
    const int tid = threadIdx.x;

    if (bid < 128) {
        __shared__ float t[32][33];
        const int tx = tid & 31, ty = tid >> 5;
        int n0 = (bid & 15) * 32, k0 = (bid >> 4) * 32;
#pragma unroll
        for (int i = 0; i < 4; ++i)
            t[ty + 8 * i][tx] = gw[(long)(k0 + ty + 8 * i) * NH + n0 + tx];
        __syncthreads();
#pragma unroll
        for (int i = 0; i < 4; ++i) {
            float v = t[tx][ty + 8 * i];
            __half h = __float2half_rn(v);
            __half l = __float2half_rn(v - __half2float(h));
            size_t idx = (size_t)(n0 + ty + 8 * i) * DIN + k0 + tx;
            g_gwh[idx] = h;
            g_gwl[idx] = l;
        }
        return;
    }
    if (bid < 640) {
        int i = (bid - 128) * 256 + tid;
        g_logits[i] = gob[i & 15];
        return;
    }
    if (tid < NE) g_cnt[tid] = 0;
    if (tid < 64) g_tilecnt[tid] = 0;
}

// ---------------------------------------------------------------------------
// prep_expert: 3 weight transposes -> single fp16 planes. (unchanged)
// ---------------------------------------------------------------------------
__global__ __launch_bounds__(256) void prep_expert_kernel(
    const float* __restrict__ w1, const float* __restrict__ w2,
    const float* __restrict__ w3)
{
    const int bid = blockIdx.x;
    const int tid = threadIdx.x;
    __shared__ float t[32][33];
    const int tx = tid & 31, ty = tid >> 5;

    const float* src; long rs; int K, N, e, n0, k0;
    __half* dh;
    if (bid < 2048) {                    // w1
        int l = bid;
        e = l >> 7; int r = l & 127;
        n0 = (r & 15) * 32; k0 = (r >> 4) * 32;
        src = w1 + e * NH; rs = (long)NE * NH; K = DIN; N = NH;
        dh = g_w1T;
    } else if (bid < 6144) {             // w2
        int l = bid - 2048;
        e = l >> 8; int r = l & 255;
        n0 = (r & 15) * 32; k0 = (r >> 4) * 32;
        src = w2 + e * NH; rs = (long)NE * NH; K = NH; N = NH;
        dh = g_w2T;
    } else {                             // w3
        int l = bid - 6144;
        e = l >> 7; int r = l & 127;
        n0 = (r & 7) * 32; k0 = (r >> 3) * 32;
        src = w3 + e * DOUT; rs = (long)NE * DOUT; K = NH; N = DOUT;
        dh = g_w3T;
    }
    dh += (size_t)e * N * K;

#pragma unroll
    for (int i = 0; i < 4; ++i)
        t[ty + 8 * i][tx] = src[(long)(k0 + ty + 8 * i) * rs + n0 + tx];
    __syncthreads();
#pragma unroll
    for (int i = 0; i < 4; ++i)
        dh[(size_t)(n0 + ty + 8 * i) * K + k0 + tx] = __float2half_rn(t[tx][ty + 8 * i]);
}

// ---------------------------------------------------------------------------
// gate_mma: inline x split (fp32 -> persistent hi/lo A in smem, xh -> gmem)
// + 3-product split-fp16 hidden GEMM (B 2-stage) + partial logits + routing.
// Grid (64, 2). smem 192KB:
//   [0,64K)      A-hi chunks 0..7 (persistent)
//   [64K,128K)   A-lo chunks 0..7 (persistent; conversion overwrites fp32)
//   [64K,192K)   fp32 x staging during prologue (chunk c at 64K + c*16K)
//   [128K,192K)  B stages: 2 x 32K (Bhi 16K | Blo 16K)
// ---------------------------------------------------------------------------
#define FP32OFF 65536
#define ALOOFF  65536
#define BOFF2   131072
#define BSTG    32768
#define GSM     196608
#define HSP     264
#define GPAD    20

__global__ __launch_bounds__(512, 1) void gate_mma_kernel(
    const float* __restrict__ x, const float* __restrict__ gb,
    const float* __restrict__ gow)
{
    const int tile  = blockIdx.x;
    const int nbase = blockIdx.y * 256;

    extern __shared__ char smp[];
    const uint32_t smb = smem_u32(smp);
    __shared__ float sbias[256];
    __shared__ int   s_flag;

    const int tid  = threadIdx.x;
    const int wid  = tid >> 5, lane = tid & 31;
    const int wm   = wid & 3,  wn   = wid >> 2;

    if (tid < 256) sbias[tid] = gb[nbase + tid];

    // ---- prologue: load fp32 x tile (16 CP16 per thread) ----
#pragma unroll
    for (int i = 0; i < 16; ++i) {
        int idx = tid + i * 512;             // 0..8191
        int c = idx >> 10, r = (idx >> 3) & 127, u8 = idx & 7;
        CP16(smb + FP32OFF + c * 16384 + r * 128 + u8 * 16,
             x + (size_t)(tile * 128 + r) * DIN + c * 32 + u8 * 4);
    }
    CP_COMMIT();
    CP_WAIT(0);
    __syncthreads();

    // ---- convert fp32 -> hi/lo sw32 chunks (in-place safe; see analysis) ----
    {
        const int row = tid >> 2, u = tid & 3;
#pragma unroll
        for (int c = 0; c < 8; ++c) {
            const float* src = (const float*)(smp + FP32OFF + c * 16384 +
                                              row * 128 + u * 32);
            float4 a = ((const float4*)src)[0];
            float4 b = ((const float4*)src)[1];
            __syncthreads();   // all reads of chunk c done before overwrite
            __half h0 = __float2half_rn(a.x), h1 = __float2half_rn(a.y);
            __half h2 = __float2half_rn(a.z), h3 = __float2half_rn(a.w);
            __half h4 = __float2half_rn(b.x), h5 = __float2half_rn(b.y);
            __half h6 = __float2half_rn(b.z), h7 = __float2half_rn(b.w);
            __half l0 = __float2half_rn(a.x - __half2float(h0));
            __half l1 = __float2half_rn(a.y - __half2float(h1));
            __half l2 = __float2half_rn(a.z - __half2float(h2));
            __half l3 = __float2half_rn(a.w - __half2float(h3));
            __half l4 = __float2half_rn(b.x - __half2float(h4));
            __half l5 = __float2half_rn(b.y - __half2float(h5));
            __half l6 = __float2half_rn(b.z - __half2float(h6));
            __half l7 = __float2half_rn(b.w - __half2float(h7));
            __half2 H01 = __halves2half2(h0, h1), H23 = __halves2half2(h2, h3);
            __half2 H45 = __halves2half2(h4, h5), H67 = __halves2half2(h6, h7);
            __half2 L01 = __halves2half2(l0, l1), L23 = __halves2half2(l2, l3);
            __half2 L45 = __halves2half2(l4, l5), L67 = __halves2half2(l6, l7);
            uint4 H = make_uint4(*(uint32_t*)&H01, *(uint32_t*)&H23,
                                 *(uint32_t*)&H45, *(uint32_t*)&H67);
            uint4 L = make_uint4(*(uint32_t*)&L01, *(uint32_t*)&L23,
                                 *(uint32_t*)&L45, *(uint32_t*)&L67);
            *(uint4*)(smp + c * 8192 + sw32(row, u))          = H;
            *(uint4*)(smp + ALOOFF + c * 8192 + sw32(row, u)) = L;
            if (nbase == 0)
                *(uint4*)(g_xh + (size_t)(tile * 128 + row) * DIN + c * 32 + u * 8) = H;
        }
    }
    __syncthreads();

    // ---- B loader: gw hi/lo chunk into 2-stage buffer ----
    auto loadB = [&](int ch) {
        const int kbase = ch * 32;
        const uint32_t sb = smb + BOFF2 + (ch & 1) * BSTG;
#pragma unroll
        for (int i = 0; i < 2; ++i) {
            int idx = tid + i * 512;
            int row = idx >> 2, u = idx & 3;
            uint32_t d = sb + sw32(row, u);
            CP16(d,         g_gwh + (size_t)(nbase + row) * DIN + kbase + u * 8);
            CP16(d + 16384, g_gwl + (size_t)(nbase + row) * DIN + kbase + u * 8);
        }
        CP_COMMIT();
    };

    float acc[2][8][4];
#pragma unroll
    for (int mf = 0; mf < 2; ++mf)
#pragma unroll
        for (int nf = 0; nf < 8; ++nf)
#pragma unroll
            for (int j = 0; j < 4; ++j) acc[mf][nf][j] = 0.f;

    loadB(0);
    loadB(1);

    const int NCH = DIN / 32;
    for (int ch = 0; ch < NCH; ++ch) {
        CP_WAIT(1);
        __syncthreads();

        const uint32_t aHI = smb + ch * 8192;
        const uint32_t aLO = smb + ALOOFF + ch * 8192;
        const uint32_t bHI = smb + BOFF2 + (ch & 1) * BSTG;
        const uint32_t bLO = bHI + 16384;

#pragma unroll
        for (int ks = 0; ks < 2; ++ks) {
            const int k0 = ks * 16;
            uint32_t ahi[2][4], alo[2][4];
            {
                int r_ = (lane & 7) + ((lane >> 3) & 1) * 8;
                int au = (k0 >> 3) + (lane >> 4);
#pragma unroll
                for (int mf = 0; mf < 2; ++mf) {
                    int r = wm * 32 + mf * 16 + r_;
                    LDSM4(ahi[mf], aHI + sw32(r, au));
                    LDSM4(alo[mf], aLO + sw32(r, au));
                }
            }
#pragma unroll
            for (int g = 0; g < 2; ++g) {
                uint32_t bhi[4][2], blo[4][2];
                int n_ = (lane & 7) + (lane >> 4) * 8;
                int bu = (k0 >> 3) + ((lane >> 3) & 1);
#pragma unroll
                for (int nb = 0; nb < 2; ++nb) {
                    int n = wn * 64 + (g * 2 + nb) * 16 + n_;
                    uint32_t r4[4];
                    LDSM4(r4, bHI + sw32(n, bu));
                    bhi[2 * nb][0] = r4[0]; bhi[2 * nb][1] = r4[1];
                    bhi[2 * nb + 1][0] = r4[2]; bhi[2 * nb + 1][1] = r4[3];
                    LDSM4(r4, bLO + sw32(n, bu));
                    blo[2 * nb][0] = r4[0]; blo[2 * nb][1] = r4[1];
                    blo[2 * nb + 1][0] = r4[2]; blo[2 * nb + 1][1] = r4[3];
                }
#pragma unroll
                for (int mf = 0; mf < 2; ++mf)
#pragma unroll
                    for (int nf = 0; nf < 4; ++nf)
                        MMA16816H(acc[mf][g * 4 + nf], ahi[mf], bhi[nf]);
#pragma unroll
                for (int mf = 0; mf < 2; ++mf)
#pragma unroll
                    for (int nf = 0; nf < 4; ++nf)
                        MMA16816H(acc[mf][g * 4 + nf], alo[mf], bhi[nf]);
#pragma unroll
                for (int mf = 0; mf < 2; ++mf)
#pragma unroll
                    for (int nf = 0; nf < 4; ++nf)
                        MMA16816H(acc[mf][g * 4 + nf], ahi[mf], blo[nf]);
            }
        }
        __syncthreads();
        if (ch + 2 < NCH) loadB(ch + 2);
        else              CP_COMMIT();          // keep wait-count invariant
    }
    __syncthreads();

    // ---- epilogue: partial logits (FMA2-packed across experts) ----
    float* Hsm  = (float*)smp;            // [64][HSP]
    float* gowS = Hsm + 64 * HSP;         // [256][GPAD]
    for (int idx = tid; idx < 256 * NE; idx += 512) {
        int r = idx >> 4, c = idx & 15;
        gowS[r * GPAD + c] = gow[(nbase + r) * NE + c];
    }

    const int grp = lane >> 2, t2 = (lane & 3) * 2;
#pragma unroll
    for (int hp = 0; hp < 2; ++hp) {
        if (hp == 1) __syncthreads();
        if ((wm >> 1) == hp) {
            int rbase = (wm & 1) * 32;
#pragma unroll
            for (int mf = 0; mf < 2; ++mf)
#pragma unroll
                for (int nf = 0; nf < 8; ++nf) {
                    const float* c = acc[mf][nf];
                    int col = wn * 64 + nf * 8 + t2;
#pragma unroll
                    for (int h8 = 0; h8 < 2; ++h8) {
                        int lr = rbase + mf * 16 + grp + h8 * 8;
                        Hsm[lr * HSP + col]     = fmaxf(c[h8 * 2] + sbias[col], 0.f);
                        Hsm[lr * HSP + col + 1] = fmaxf(c[h8 * 2 + 1] + sbias[col + 1], 0.f);
                    }
                }
        }
        __syncthreads();

        const int t = tid >> 3, s = tid & 7;
        unsigned long long lacc[8];
#pragma unroll
        for (int p = 0; p < 8; ++p) DUP2(lacc[p], 0.f);
#pragma unroll 4
        for (int i = 0; i < 32; ++i) {
            int rk = s + 8 * i;
            float v = Hsm[t * HSP + rk];
            unsigned long long vv;
            DUP2(vv, v);
            const ulonglong2* gp = (const ulonglong2*)(gowS + rk * GPAD);
            ulonglong2 g0 = gp[0], g1 = gp[1], g2 = gp[2], g3 = gp[3];
            FMA2(lacc[0], g0.x, vv);  FMA2(lacc[1], g0.y, vv);
            FMA2(lacc[2], g1.x, vv);  FMA2(lacc[3], g1.y, vv);
            FMA2(lacc[4], g2.x, vv);  FMA2(lacc[5], g2.y, vv);
            FMA2(lacc[6], g3.x, vv);  FMA2(lacc[7], g3.y, vv);
        }
        float l[NE];
#pragma unroll
        for (int p = 0; p < 8; ++p) UNPK(l[2 * p], l[2 * p + 1], lacc[p]);
#pragma unroll
        for (int m2 = 1; m2 < 8; m2 <<= 1)
#pragma unroll
            for (int e = 0; e < NE; ++e)
                l[e] += __shfl_xor_sync(0xffffffffu, l[e], m2);

        int tok = tile * 128 + hp * 64 + t;
        atomicAdd(&g_logits[tok * NE + 2 * s],     l[2 * s]);
        atomicAdd(&g_logits[tok * NE + 2 * s + 1], l[2 * s + 1]);
    }

    // ---- routing: last CTA of this tile does top-2 + softmax + append ----
    __threadfence();
    __syncthreads();
    if (tid == 0) s_flag = atomicAdd(&g_tilecnt[tile], 1);
    __syncthreads();
    if (s_flag == 1 && tid < 128) {
        int tok = tile * 128 + tid;
        float v0 = -1e30f, v1 = -1e30f;
        int i0 = 0, i1 = 0;
#pragma unroll
        for (int e = 0; e < NE; ++e) {
            float lg = __ldcg(&g_logits[tok * NE + e]);
            if (lg > v0)      { v1 = v0; i1 = i0; v0 = lg; i0 = e; }
            else if (lg > v1) { v1 = lg; i1 = e; }
        }
        float e1 = __expf(v1 - v0);
        float sden = 1.f + e1;
        int p0 = atomicAdd(&g_cnt[i0], 1);
        g_rtok[i0 * NTOK + p0]  = tok;
        g_rgate[i0 * NTOK + p0] = 1.f / sden;
        int p1 = atomicAdd(&g_cnt[i1], 1);
        g_rtok[i1 * NTOK + p1]  = tok;
        g_rgate[i1 * NTOK + p1] = e1 / sden;
    }
}

// ---------------------------------------------------------------------------
// expert_fused: one CTA per (expert, 128-token tile) runs all 3 layers.
// (byte-identical to round 14/16)
// ---------------------------------------------------------------------------
#define H1OFF 0
#define H2OFF 131072
#define BOFF  196608
#define EB    16384
#define SMEXP 229376

__global__ __launch_bounds__(512, 1) void expert_fused_kernel(
    const float* __restrict__ b1, const float* __restrict__ b2,
    const float* __restrict__ b3, float* __restrict__ outp)
{
    const int e    = blockIdx.y;
    const int tile = blockIdx.x;
    const int cnt  = g_cnt[e];
    if (tile * 128 >= cnt) return;
    const int m = min(128, cnt - tile * 128);

    extern __shared__ char smp[];
    const uint32_t smb = smem_u32(smp);
    __shared__ int   toks[128];
    __shared__ float gts[128];
    __shared__ float sbias[256];

    const int tid  = threadIdx.x;
    const int wid  = tid >> 5, lane = tid & 31;
    const int wm   = wid & 3,  wn   = wid >> 2;
    const int grp  = lane >> 2, t2 = (lane & 3) * 2;

    if (tid < 128) {
        int i = tile * 128 + tid;
        bool v = (i < cnt);
        toks[tid] = v ? g_rtok[e * NTOK + i] : 0;
        gts[tid]  = v ? g_rgate[e * NTOK + i] : 0.f;
    }
    __syncthreads();

    float acc[2][8][4];

    auto zero_acc = [&]() {
#pragma unroll
        for (int mf = 0; mf < 2; ++mf)
#pragma unroll
            for (int nf = 0; nf < 8; ++nf)
#pragma unroll
                for (int j = 0; j < 4; ++j) acc[mf][nf][j] = 0.f;
    };

    auto loadB = [&](const __half* Bp, int kstride, int ch) {
        const int kbase = ch * 32;
        const uint32_t sb = smb + BOFF + (ch & 1) * EB;
#pragma unroll
        for (int i = 0; i < 2; ++i) {
            int idx = tid + i * 512;
            int row = idx >> 2, u = idx & 3;
            CP16(sb + sw32(row, u), Bp + (size_t)row * kstride + kbase + u * 8);
        }
    };

    auto compute_chunk = [&](uint32_t aB, uint32_t bB) {
#pragma unroll
        for (int ks = 0; ks < 2; ++ks) {
            const int k0 = ks * 16;
            uint32_t af[2][4];
            {
                int r_ = (lane & 7) + ((lane >> 3) & 1) * 8;
                int au = (k0 >> 3) + (lane >> 4);
#pragma unroll
                for (int mf = 0; mf < 2; ++mf) {
                    int r = wm * 32 + mf * 16 + r_;
                    LDSM4(af[mf], aB + sw32(r, au));
                }
            }
#pragma unroll
            for (int g = 0; g < 2; ++g) {
                uint32_t bf[4][2];
                int n_ = (lane & 7) + (lane >> 4) * 8;
                int bu = (k0 >> 3) + ((lane >> 3) & 1);
#pragma unroll
                for (int nb = 0; nb < 2; ++nb) {
                    int n = wn * 64 + (g * 2 + nb) * 16 + n_;
                    uint32_t r4[4];
                    LDSM4(r4, bB + sw32(n, bu));
                    bf[2 * nb][0] = r4[0]; bf[2 * nb][1] = r4[1];
                    bf[2 * nb + 1][0] = r4[2]; bf[2 * nb + 1][1] = r4[3];
                }
#pragma unroll
                for (int mf = 0; mf < 2; ++mf)
#pragma unroll
                    for (int nf = 0; nf < 4; ++nf)
                        MMA16816H(acc[mf][g * 4 + nf], af[mf], bf[nf]);
            }
        }
    };

    auto run_phase = [&](const __half* Bp, int kstride, int NCH, auto abase,
                         bool prologue) {
        if (prologue) {
            loadB(Bp, kstride, 0); CP_COMMIT();
            loadB(Bp, kstride, 1); CP_COMMIT();
        }
        for (int ch = 0; ch < NCH; ++ch) {
            CP_WAIT(1);
            __syncthreads();
            compute_chunk(abase(ch), smb + BOFF + (ch & 1) * EB);
            __syncthreads();
            if (ch + 2 < NCH) loadB(Bp, kstride, ch + 2);
            CP_COMMIT();
        }
    };

    auto epi_h = [&](uint32_t hbase) {
#pragma unroll
        for (int mf = 0; mf < 2; ++mf)
#pragma unroll
            for (int nf = 0; nf < 8; ++nf) {
                const float* c = acc[mf][nf];
                int col = wn * 64 + nf * 8 + t2;
                int chunk_local = wn * 2 + (nf >> 2);
                int u = nf & 3;
#pragma unroll
                for (int h8 = 0; h8 < 2; ++h8) {
                    int r = wm * 32 + mf * 16 + grp + h8 * 8;
                    __half2 h = __floats2half2_rn(
                        fmaxf(c[h8 * 2]     + sbias[col], 0.f),
                        fmaxf(c[h8 * 2 + 1] + sbias[col + 1], 0.f));
                    *(uint32_t*)(smp + hbase + chunk_local * 8192 +
                                 sw32(r, u) + t2 * 2) = *(uint32_t*)&h;
                }
            }
    };

    const __half* w1p = g_w1T + (size_t)e * NH * DIN;
    const __half* w2p = g_w2T + (size_t)e * NH * NH;
    const __half* w3p = g_w3T + (size_t)e * DOUT * NH;

    // ---- L1 ----
    {
#pragma unroll
        for (int c = 0; c < 8; ++c) {
            int row = tid >> 2, u = tid & 3;
            CP16(smb + H2OFF + c * 8192 + sw32(row, u),
                 g_xh + (size_t)toks[row] * DIN + c * 32 + u * 8);
        }
        loadB(w1p, DIN, 0); CP_COMMIT();
        loadB(w1p, DIN, 1); CP_COMMIT();

        auto abaseX = [&](int ch) { return smb + H2OFF + ch * 8192; };
#pragma unroll
        for (int half = 0; half < 2; ++half) {
            if (tid < 256) sbias[tid] = b1[e * NH + half * 256 + tid];
            zero_acc();
            run_phase(w1p + (size_t)half * 256 * DIN, DIN, DIN / 32, abaseX,
                      half == 1);
            epi_h(H1OFF + half * 65536);
            __syncthreads();
        }
    }

    // ---- L2 ----
    {
        auto abaseH1 = [&](int ch) { return smb + H1OFF + ch * 8192; };
#pragma unroll
        for (int half = 0; half < 2; ++half) {
            if (tid < 256) sbias[tid] = b2[e * NH + half * 256 + tid];
            zero_acc();
            run_phase(w2p + (size_t)half * 256 * NH, NH, NH / 32, abaseH1, true);
            epi_h(half == 0 ? H2OFF : H1OFF);
            __syncthreads();
        }
    }

    // ---- L3 ----
    {
        if (tid < 256) sbias[tid] = b3[e * DOUT + tid];
        zero_acc();
        auto abaseH2 = [&](int ch) {
            return (ch < 8) ? (smb + H2OFF + ch * 8192)
                            : (smb + H1OFF + (ch - 8) * 8192);
        };
        run_phase(w3p, NH, NH / 32, abaseH2, true);

#pragma unroll
        for (int mf = 0; mf < 2; ++mf)
#pragma unroll
            for (int nf = 0; nf < 8; ++nf) {
                const float* c = acc[mf][nf];
                const int col = wn * 64 + nf * 8 + t2;
#pragma unroll
                for (int h8 = 0; h8 < 2; ++h8) {
                    const int r = wm * 32 + mf * 16 + grp + h8 * 8;
                    if (r < m) {
                        float g = gts[r];
                        float* orow = outp + (size_t)toks[r] * DOUT + col;
                        atomicAdd(orow,     g * (c[h8 * 2]     + sbias[col]));
                        atomicAdd(orow + 1, g * (c[h8 * 2 + 1] + sbias[col + 1]));
                    }
                }
            }
    }
}

// ---------------------------------------------------------------------------
extern "C" void kernel_launch(void* const* d_in, const int* in_sizes, int n_in,
                              void* d_out, int out_size)
{
    const float* x   = (const float*)d_in[0];
    const float* gw  = (const float*)d_in[1];
    const float* gb  = (const float*)d_in[2];
    const float* gow = (const float*)d_in[3];
    const float* gob = (const float*)d_in[4];
    const float* w1  = (const float*)d_in[5];
    const float* b1  = (const float*)d_in[6];
    const float* w2  = (const float*)d_in[7];
    const float* b2  = (const float*)d_in[8];
    const float* w3  = (const float*)d_in[9];
    const float* b3  = (const float*)d_in[10];
    float* out = (float*)d_out;

    static cudaStream_t s_side = nullptr;
    static cudaEvent_t  s_evF = nullptr, s_evJ = nullptr;
    if (!s_side) {
        cudaStreamCreateWithFlags(&s_side, cudaStreamNonBlocking);
        cudaEventCreateWithFlags(&s_evF, cudaEventDisableTiming);
        cudaEventCreateWithFlags(&s_evJ, cudaEventDisableTiming);
    }

    cudaFuncSetAttribute(gate_mma_kernel, cudaFuncAttributeMaxDynamicSharedMemorySize, GSM);
    cudaFuncSetAttribute(expert_fused_kernel, cudaFuncAttributeMaxDynamicSharedMemorySize, SMEXP);

    // ---- fork ----
    cudaEventRecord(s_evF, 0);
    cudaStreamWaitEvent(s_side, s_evF, 0);

    prep_gate_kernel<<<641, 256>>>(gw, gob);                     // #1 (main, ~1.5us)
    cudaMemsetAsync(out, 0, (size_t)NTOK * DOUT * sizeof(float), s_side);
    prep_expert_kernel<<<8192, 256, 0, s_side>>>(w1, w2, w3);    // #2 (side)
    gate_mma_kernel<<<dim3(64, 2), 512, GSM>>>(x, gb, gow);      // #3 (main)

    // ---- join ----
    cudaEventRecord(s_evJ, s_side);
    cudaStreamWaitEvent(0, s_evJ, 0);

    expert_fused_kernel<<<dim3(64, NE), 512, SMEXP>>>(b1, b2, b3, out);  // #4 -> ncu
}